// round 11
// baseline (speedup 1.0000x reference)
#include <cuda_runtime.h>
#include <cstdint>

// StrictProjectionBlock: 4M independent 3x3 fp32 matrices.
//   Q = X/||X||_F ; 4x:  S = Q^T Q - 1.5I;  Q <- Q * (0.5*S^2 + 0.875I)
//
// R11 = R10 with the R = Q*M pass restructured row-by-row so peak live state
// drops from 24 to ~21 u64 (q9+m6+row3), allowing __launch_bounds__(128,10)
// (<=51 regs) -> 10 CTAs/SM = 40 resident warps (up from 36).
// Depth-2 cp.async loads, TMA bulk stores, packed fp32x2 math, strided
// lane->matrix layout, pass-ordered FMAs for operand-collector reuse.

using u64 = unsigned long long;

__device__ __forceinline__ u64 pk2(float lo, float hi) {
    u64 r; asm("mov.b64 %0, {%1,%2};" : "=l"(r) : "f"(lo), "f"(hi)); return r;
}
__device__ __forceinline__ void upk2(u64 v, float& lo, float& hi) {
    asm("mov.b64 {%0,%1}, %2;" : "=f"(lo), "=f"(hi) : "l"(v));
}
__device__ __forceinline__ u64 fma2(u64 a, u64 b, u64 c) {
    u64 d; asm("fma.rn.f32x2 %0, %1, %2, %3;" : "=l"(d) : "l"(a), "l"(b), "l"(c)); return d;
}
__device__ __forceinline__ u64 mul2(u64 a, u64 b) {
    u64 d; asm("mul.rn.f32x2 %0, %1, %2;" : "=l"(d) : "l"(a), "l"(b)); return d;
}
__device__ __forceinline__ uint32_t smem_u32(const void* p) {
    uint32_t a;
    asm("{ .reg .u64 t; cvta.to.shared.u64 t, %1; cvt.u32.u64 %0, t; }" : "=r"(a) : "l"(p));
    return a;
}
__device__ __forceinline__ void cpa16(uint32_t s, const void* g) {
    asm volatile("cp.async.cg.shared.global [%0], [%1], 16;" :: "r"(s), "l"(g));
}
__device__ __forceinline__ void cpa_commit() { asm volatile("cp.async.commit_group;"); }
__device__ __forceinline__ void cpa_wait1()  { asm volatile("cp.async.wait_group 1;"); }
__device__ __forceinline__ void cpa_wait0()  { asm volatile("cp.async.wait_group 0;"); }

__device__ __forceinline__ void bulk_store(u64 gdst, uint32_t ssrc, uint32_t bytes) {
    asm volatile("cp.async.bulk.global.shared::cta.bulk_group [%0], [%1], %2;"
                 :: "l"(gdst), "r"(ssrc), "r"(bytes) : "memory");
}
__device__ __forceinline__ void bulk_commit() {
    asm volatile("cp.async.bulk.commit_group;" ::: "memory");
}
__device__ __forceinline__ void bulk_wait_read0() {
    asm volatile("cp.async.bulk.wait_group.read 0;" ::: "memory");
}
__device__ __forceinline__ void bulk_wait_all0() {
    asm volatile("cp.async.bulk.wait_group 0;" ::: "memory");
}
__device__ __forceinline__ void fence_async_shared() {
    asm volatile("fence.proxy.async.shared::cta;" ::: "memory");
}

constexpr int THREADS = 128;
constexpr int WARPS   = THREADS / 32;     // 4
constexpr int WMT     = 64;               // matrices per warp-tile (2/thread)
constexpr int WFL     = WMT * 9;          // 576 floats
constexpr int WFLB    = WFL * 4;          // 2304 bytes per tile

constexpr u64 C_HALF = 0x3F0000003F000000ULL;  // ( 0.5  , 0.5  )
constexpr u64 C_M15  = 0xBFC00000BFC00000ULL;  // (-1.5  ,-1.5  )
constexpr u64 C_7o8  = 0x3F6000003F600000ULL;  // ( 0.875, 0.875)

// scalar fallback for remainder matrices (n_mat % 64 != 0; unused for 4M)
__device__ void project1(float* q) {
    float ss = 0.f;
    #pragma unroll
    for (int i = 0; i < 9; i++) ss += q[i] * q[i];
    float inv = rsqrtf(ss);
    #pragma unroll
    for (int i = 0; i < 9; i++) q[i] *= inv;
    #pragma unroll
    for (int l = 0; l < 4; l++) {
        float n00 = q[0]*q[0]+q[3]*q[3]+q[6]*q[6];
        float n01 = q[0]*q[1]+q[3]*q[4]+q[6]*q[7];
        float n02 = q[0]*q[2]+q[3]*q[5]+q[6]*q[8];
        float n11 = q[1]*q[1]+q[4]*q[4]+q[7]*q[7];
        float n12 = q[1]*q[2]+q[4]*q[5]+q[7]*q[8];
        float n22 = q[2]*q[2]+q[5]*q[5]+q[8]*q[8];
        float s00 = n00-1.5f, s11 = n11-1.5f, s22 = n22-1.5f;
        float m00 = 0.5f*(s00*s00+n01*n01+n02*n02)+0.875f;
        float m01 = 0.5f*(s00*n01+n01*s11+n02*n12);
        float m02 = 0.5f*(s00*n02+n01*n12+n02*s22);
        float m11 = 0.5f*(n01*n01+s11*s11+n12*n12)+0.875f;
        float m12 = 0.5f*(n01*n02+s11*n12+n12*s22);
        float m22 = 0.5f*(n02*n02+n12*n12+s22*s22)+0.875f;
        float r0 = q[0]*m00+q[1]*m01+q[2]*m02;
        float r1 = q[0]*m01+q[1]*m11+q[2]*m12;
        float r2 = q[0]*m02+q[1]*m12+q[2]*m22;
        float r3 = q[3]*m00+q[4]*m01+q[5]*m02;
        float r4 = q[3]*m01+q[4]*m11+q[5]*m12;
        float r5 = q[3]*m02+q[4]*m12+q[5]*m22;
        float r6 = q[6]*m00+q[7]*m01+q[8]*m02;
        float r7 = q[6]*m01+q[7]*m11+q[8]*m12;
        float r8 = q[6]*m02+q[7]*m12+q[8]*m22;
        q[0]=r0; q[1]=r1; q[2]=r2; q[3]=r3; q[4]=r4;
        q[5]=r5; q[6]=r6; q[7]=r7; q[8]=r8;
    }
}

__global__ void __launch_bounds__(THREADS, 10)
strict_projection_kernel(const float* __restrict__ in,
                         float* __restrict__ out,
                         int n_mat, int n_wt)
{
    __shared__ float smem[WARPS][2][WFL];    // 18,432 B -> 10 CTAs/SM ok

    const int lane = threadIdx.x & 31;
    const int wid  = threadIdx.x >> 5;

    // ---- remainder matrices (n_mat % 64), block 0 / warp 0 ----
    if (blockIdx.x == 0 && wid == 0) {
        const int rem_base = n_wt * WMT;
        for (int m = rem_base + lane; m < n_mat; m += 32) {
            float q[9];
            #pragma unroll
            for (int i = 0; i < 9; i++) q[i] = in[(size_t)m * 9 + i];
            project1(q);
            #pragma unroll
            for (int i = 0; i < 9; i++) out[(size_t)m * 9 + i] = q[i];
        }
    }

    const int wgid    = blockIdx.x * WARPS + wid;
    const int wstride = gridDim.x * WARPS;
    if (wgid >= n_wt) return;

    const uint32_t sb[2] = { smem_u32(&smem[wid][0][0]), smem_u32(&smem[wid][1][0]) };

    const size_t stepB = (size_t)wstride * WFLB;
    const float4* gpre = reinterpret_cast<const float4*>(in) + (size_t)wgid * (WFL / 4);
    u64 gdst = (u64)(uintptr_t)out + (u64)wgid * WFLB;

    auto prefetch = [&](const float4* g, uint32_t s) {
        #pragma unroll
        for (int k = 0; k < 4; k++)
            cpa16(s + (uint32_t)(lane + 32 * k) * 16u, g + lane + 32 * k);
        if (lane < 16)
            cpa16(s + (uint32_t)(128 + lane) * 16u, g + 128 + lane);
    };

    prefetch(gpre, sb[0]);
    cpa_commit();
    gpre += stepB / 16;

    int buf = 0;
    for (int t = wgid; t < n_wt; t += wstride, buf ^= 1) {
        const bool have_next = (t + wstride) < n_wt;
        if (have_next) {
            if (lane == 0) bulk_wait_read0();   // TMA done reading buf^1
            __syncwarp();
            prefetch(gpre, sb[buf ^ 1]);
            cpa_commit();
            cpa_wait1();
            gpre += stepB / 16;
        } else {
            cpa_wait0();
        }
        __syncwarp();

        // ---- strided lane->matrix: A = tile[lane], B = tile[lane+32] ----
        const float* A = &smem[wid][buf][lane * 9];
        const float* B = A + 32 * 9;

        u64 q0 = pk2(A[0], B[0]), q1 = pk2(A[1], B[1]), q2 = pk2(A[2], B[2]);
        u64 q3 = pk2(A[3], B[3]), q4 = pk2(A[4], B[4]), q5 = pk2(A[5], B[5]);
        u64 q6 = pk2(A[6], B[6]), q7 = pk2(A[7], B[7]), q8 = pk2(A[8], B[8]);

        // ---- Frobenius normalize ----
        u64 ss = mul2(q0, q0);
        ss = fma2(q1, q1, ss); ss = fma2(q2, q2, ss);
        ss = fma2(q3, q3, ss); ss = fma2(q4, q4, ss);
        ss = fma2(q5, q5, ss); ss = fma2(q6, q6, ss);
        ss = fma2(q7, q7, ss); ss = fma2(q8, q8, ss);
        float sa, sbf; upk2(ss, sa, sbf);
        const u64 inv = pk2(rsqrtf(sa), rsqrtf(sbf));
        q0 = mul2(q0, inv); q1 = mul2(q1, inv); q2 = mul2(q2, inv);
        q3 = mul2(q3, inv); q4 = mul2(q4, inv); q5 = mul2(q5, inv);
        q6 = mul2(q6, inv); q7 = mul2(q7, inv); q8 = mul2(q8, inv);

        #pragma unroll
        for (int layer = 0; layer < 4; ++layer) {
            // S = Q^T Q - 1.5I : row passes, slot-A shared within pass
            u64 s00 = fma2(q0, q0, C_M15);
            u64 s01 = mul2(q0, q1);
            u64 s02 = mul2(q0, q2);
            u64 s11 = fma2(q1, q1, C_M15);
            u64 s12 = mul2(q1, q2);
            u64 s22 = fma2(q2, q2, C_M15);

            s00 = fma2(q3, q3, s00);
            s01 = fma2(q3, q4, s01);
            s02 = fma2(q3, q5, s02);
            s11 = fma2(q4, q4, s11);
            s12 = fma2(q4, q5, s12);
            s22 = fma2(q5, q5, s22);

            s00 = fma2(q6, q6, s00);
            s01 = fma2(q6, q7, s01);
            s02 = fma2(q6, q8, s02);
            s11 = fma2(q7, q7, s11);
            s12 = fma2(q7, q8, s12);
            s22 = fma2(q8, q8, s22);

            // T = S^2 : row passes over S (s stays live, t builds)
            u64 t00 = mul2(s00, s00);
            u64 t01 = mul2(s00, s01);
            u64 t02 = mul2(s00, s02);
            u64 t11 = mul2(s01, s01);
            u64 t12 = mul2(s01, s02);
            u64 t22 = mul2(s02, s02);

            t00 = fma2(s01, s01, t00);
            t01 = fma2(s01, s11, t01);
            t02 = fma2(s01, s12, t02);
            t11 = fma2(s11, s11, t11);
            t12 = fma2(s11, s12, t12);
            t22 = fma2(s12, s12, t22);

            t00 = fma2(s02, s02, t00);
            t01 = fma2(s02, s12, t01);
            t02 = fma2(s02, s22, t02);
            t11 = fma2(s12, s12, t11);
            t12 = fma2(s12, s22, t12);
            t22 = fma2(s22, s22, t22);

            // M = 0.5*T + 0.875I  (reuse s registers for m)
            u64 m00 = fma2(C_HALF, t00, C_7o8);
            u64 m01 = mul2(C_HALF, t01);
            u64 m02 = mul2(C_HALF, t02);
            u64 m11 = fma2(C_HALF, t11, C_7o8);
            u64 m12 = mul2(C_HALF, t12);
            u64 m22 = fma2(C_HALF, t22, C_7o8);

            // R = Q * M : row-by-row, 3 temps, overwrite that row's q
            // (keeps peak live at q9+m6+3 = 18 u64 instead of 24)
            {
                u64 r0 = mul2(q0, m00);
                u64 r1 = mul2(q0, m01);
                u64 r2 = mul2(q0, m02);
                r0 = fma2(q1, m01, r0);
                r1 = fma2(q1, m11, r1);
                r2 = fma2(q1, m12, r2);
                q0 = fma2(q2, m02, r0);
                q1 = fma2(q2, m12, r1);
                q2 = fma2(q2, m22, r2);
            }
            {
                u64 r3 = mul2(q3, m00);
                u64 r4 = mul2(q3, m01);
                u64 r5 = mul2(q3, m02);
                r3 = fma2(q4, m01, r3);
                r4 = fma2(q4, m11, r4);
                r5 = fma2(q4, m12, r5);
                q3 = fma2(q5, m02, r3);
                q4 = fma2(q5, m12, r4);
                q5 = fma2(q5, m22, r5);
            }
            {
                u64 r6 = mul2(q6, m00);
                u64 r7 = mul2(q6, m01);
                u64 r8 = mul2(q6, m02);
                r6 = fma2(q7, m01, r6);
                r7 = fma2(q7, m11, r7);
                r8 = fma2(q7, m12, r8);
                q6 = fma2(q8, m02, r6);
                q7 = fma2(q8, m12, r7);
                q8 = fma2(q8, m22, r8);
            }
        }

        // ---- writeback: scalar halves (pair halves are free) ----
        {
            float* WA = &smem[wid][buf][lane * 9];
            float* WB = WA + 32 * 9;
            float x, y;
            upk2(q0, x, y); WA[0] = x; WB[0] = y;
            upk2(q1, x, y); WA[1] = x; WB[1] = y;
            upk2(q2, x, y); WA[2] = x; WB[2] = y;
            upk2(q3, x, y); WA[3] = x; WB[3] = y;
            upk2(q4, x, y); WA[4] = x; WB[4] = y;
            upk2(q5, x, y); WA[5] = x; WB[5] = y;
            upk2(q6, x, y); WA[6] = x; WB[6] = y;
            upk2(q7, x, y); WA[7] = x; WB[7] = y;
            upk2(q8, x, y); WA[8] = x; WB[8] = y;
        }
        __syncwarp();

        // ---- copy out: one TMA bulk store per warp-tile ----
        if (lane == 0) {
            fence_async_shared();
            bulk_store(gdst, sb[buf], WFLB);
            bulk_commit();
        }
        gdst += stepB;
    }

    if (lane == 0) bulk_wait_all0();
}

extern "C" void kernel_launch(void* const* d_in, const int* in_sizes, int n_in,
                              void* d_out, int out_size)
{
    const float* x = (const float*)d_in[0];
    float* out = (float*)d_out;
    const int n_mat = in_sizes[0] / 9;          // 4,000,000
    const int n_wt  = n_mat / WMT;              // 62,500 full warp-tiles
    int grid = 152 * 10;                        // 10 CTAs/SM, 40 warps/SM
    const int max_grid = (n_wt + WARPS - 1) / WARPS;
    if (grid > max_grid) grid = max_grid;
    if (grid < 1) grid = 1;
    strict_projection_kernel<<<grid, THREADS>>>(x, out, n_mat, n_wt);
}

// round 12
// speedup vs baseline: 1.0381x; 1.0381x over previous
#include <cuda_runtime.h>
#include <cstdint>

// StrictProjectionBlock: 4M independent 3x3 fp32 matrices.
//   Q = X/||X||_F ; 4x:  S = Q^T Q - 1.5I;  Q <- Q * (0.5*S^2 + 0.875I)
//
// R12 = R10 (best shape: depth-2 cp.async, TMA bulk stores, packed fp32x2,
// strided lane->matrix, 9-wide R-pass, 9 CTAs/SM) + folded normalization:
//   G = X^T X ; ss = trace(G) ; S0 = inv2*G - 1.5I ; layer-0 M scaled by inv
// saves the separate sum-sq + Q-scale prologue (294 -> 287 packed fma ops).

using u64 = unsigned long long;

__device__ __forceinline__ u64 pk2(float lo, float hi) {
    u64 r; asm("mov.b64 %0, {%1,%2};" : "=l"(r) : "f"(lo), "f"(hi)); return r;
}
__device__ __forceinline__ void upk2(u64 v, float& lo, float& hi) {
    asm("mov.b64 {%0,%1}, %2;" : "=f"(lo), "=f"(hi) : "l"(v));
}
__device__ __forceinline__ u64 fma2(u64 a, u64 b, u64 c) {
    u64 d; asm("fma.rn.f32x2 %0, %1, %2, %3;" : "=l"(d) : "l"(a), "l"(b), "l"(c)); return d;
}
__device__ __forceinline__ u64 mul2(u64 a, u64 b) {
    u64 d; asm("mul.rn.f32x2 %0, %1, %2;" : "=l"(d) : "l"(a), "l"(b)); return d;
}
__device__ __forceinline__ u64 add2(u64 a, u64 b) {
    u64 d; asm("add.rn.f32x2 %0, %1, %2;" : "=l"(d) : "l"(a), "l"(b)); return d;
}
__device__ __forceinline__ uint32_t smem_u32(const void* p) {
    uint32_t a;
    asm("{ .reg .u64 t; cvta.to.shared.u64 t, %1; cvt.u32.u64 %0, t; }" : "=r"(a) : "l"(p));
    return a;
}
__device__ __forceinline__ void cpa16(uint32_t s, const void* g) {
    asm volatile("cp.async.cg.shared.global [%0], [%1], 16;" :: "r"(s), "l"(g));
}
__device__ __forceinline__ void cpa_commit() { asm volatile("cp.async.commit_group;"); }
__device__ __forceinline__ void cpa_wait1()  { asm volatile("cp.async.wait_group 1;"); }
__device__ __forceinline__ void cpa_wait0()  { asm volatile("cp.async.wait_group 0;"); }

__device__ __forceinline__ void bulk_store(u64 gdst, uint32_t ssrc, uint32_t bytes) {
    asm volatile("cp.async.bulk.global.shared::cta.bulk_group [%0], [%1], %2;"
                 :: "l"(gdst), "r"(ssrc), "r"(bytes) : "memory");
}
__device__ __forceinline__ void bulk_commit() {
    asm volatile("cp.async.bulk.commit_group;" ::: "memory");
}
__device__ __forceinline__ void bulk_wait_read0() {
    asm volatile("cp.async.bulk.wait_group.read 0;" ::: "memory");
}
__device__ __forceinline__ void bulk_wait_all0() {
    asm volatile("cp.async.bulk.wait_group 0;" ::: "memory");
}
__device__ __forceinline__ void fence_async_shared() {
    asm volatile("fence.proxy.async.shared::cta;" ::: "memory");
}

constexpr int THREADS = 128;
constexpr int WARPS   = THREADS / 32;     // 4
constexpr int WMT     = 64;               // matrices per warp-tile (2/thread)
constexpr int WFL     = WMT * 9;          // 576 floats
constexpr int WFLB    = WFL * 4;          // 2304 bytes per tile

constexpr u64 C_HALF = 0x3F0000003F000000ULL;  // ( 0.5  , 0.5  )
constexpr u64 C_M15  = 0xBFC00000BFC00000ULL;  // (-1.5  ,-1.5  )
constexpr u64 C_7o8  = 0x3F6000003F600000ULL;  // ( 0.875, 0.875)

// scalar fallback for remainder matrices (n_mat % 64 != 0; unused for 4M)
__device__ void project1(float* q) {
    float ss = 0.f;
    #pragma unroll
    for (int i = 0; i < 9; i++) ss += q[i] * q[i];
    float inv = rsqrtf(ss);
    #pragma unroll
    for (int i = 0; i < 9; i++) q[i] *= inv;
    #pragma unroll
    for (int l = 0; l < 4; l++) {
        float n00 = q[0]*q[0]+q[3]*q[3]+q[6]*q[6];
        float n01 = q[0]*q[1]+q[3]*q[4]+q[6]*q[7];
        float n02 = q[0]*q[2]+q[3]*q[5]+q[6]*q[8];
        float n11 = q[1]*q[1]+q[4]*q[4]+q[7]*q[7];
        float n12 = q[1]*q[2]+q[4]*q[5]+q[7]*q[8];
        float n22 = q[2]*q[2]+q[5]*q[5]+q[8]*q[8];
        float s00 = n00-1.5f, s11 = n11-1.5f, s22 = n22-1.5f;
        float m00 = 0.5f*(s00*s00+n01*n01+n02*n02)+0.875f;
        float m01 = 0.5f*(s00*n01+n01*s11+n02*n12);
        float m02 = 0.5f*(s00*n02+n01*n12+n02*s22);
        float m11 = 0.5f*(n01*n01+s11*s11+n12*n12)+0.875f;
        float m12 = 0.5f*(n01*n02+s11*n12+n12*s22);
        float m22 = 0.5f*(n02*n02+n12*n12+s22*s22)+0.875f;
        float r0 = q[0]*m00+q[1]*m01+q[2]*m02;
        float r1 = q[0]*m01+q[1]*m11+q[2]*m12;
        float r2 = q[0]*m02+q[1]*m12+q[2]*m22;
        float r3 = q[3]*m00+q[4]*m01+q[5]*m02;
        float r4 = q[3]*m01+q[4]*m11+q[5]*m12;
        float r5 = q[3]*m02+q[4]*m12+q[5]*m22;
        float r6 = q[6]*m00+q[7]*m01+q[8]*m02;
        float r7 = q[6]*m01+q[7]*m11+q[8]*m12;
        float r8 = q[6]*m02+q[7]*m12+q[8]*m22;
        q[0]=r0; q[1]=r1; q[2]=r2; q[3]=r3; q[4]=r4;
        q[5]=r5; q[6]=r6; q[7]=r7; q[8]=r8;
    }
}

__global__ void __launch_bounds__(THREADS, 9)
strict_projection_kernel(const float* __restrict__ in,
                         float* __restrict__ out,
                         int n_mat, int n_wt)
{
    __shared__ float smem[WARPS][2][WFL];    // 18,432 B -> 9 CTAs/SM

    const int lane = threadIdx.x & 31;
    const int wid  = threadIdx.x >> 5;

    // ---- remainder matrices (n_mat % 64), block 0 / warp 0 ----
    if (blockIdx.x == 0 && wid == 0) {
        const int rem_base = n_wt * WMT;
        for (int m = rem_base + lane; m < n_mat; m += 32) {
            float q[9];
            #pragma unroll
            for (int i = 0; i < 9; i++) q[i] = in[(size_t)m * 9 + i];
            project1(q);
            #pragma unroll
            for (int i = 0; i < 9; i++) out[(size_t)m * 9 + i] = q[i];
        }
    }

    const int wgid    = blockIdx.x * WARPS + wid;
    const int wstride = gridDim.x * WARPS;
    if (wgid >= n_wt) return;

    const uint32_t sb[2] = { smem_u32(&smem[wid][0][0]), smem_u32(&smem[wid][1][0]) };

    const size_t stepB = (size_t)wstride * WFLB;
    const float4* gpre = reinterpret_cast<const float4*>(in) + (size_t)wgid * (WFL / 4);
    u64 gdst = (u64)(uintptr_t)out + (u64)wgid * WFLB;

    auto prefetch = [&](const float4* g, uint32_t s) {
        #pragma unroll
        for (int k = 0; k < 4; k++)
            cpa16(s + (uint32_t)(lane + 32 * k) * 16u, g + lane + 32 * k);
        if (lane < 16)
            cpa16(s + (uint32_t)(128 + lane) * 16u, g + 128 + lane);
    };

    prefetch(gpre, sb[0]);
    cpa_commit();
    gpre += stepB / 16;

    int buf = 0;
    for (int t = wgid; t < n_wt; t += wstride, buf ^= 1) {
        const bool have_next = (t + wstride) < n_wt;
        if (have_next) {
            if (lane == 0) bulk_wait_read0();   // TMA done reading buf^1
            __syncwarp();
            prefetch(gpre, sb[buf ^ 1]);
            cpa_commit();
            cpa_wait1();
            gpre += stepB / 16;
        } else {
            cpa_wait0();
        }
        __syncwarp();

        // ---- strided lane->matrix: A = tile[lane], B = tile[lane+32] ----
        const float* A = &smem[wid][buf][lane * 9];
        const float* B = A + 32 * 9;

        u64 q0 = pk2(A[0], B[0]), q1 = pk2(A[1], B[1]), q2 = pk2(A[2], B[2]);
        u64 q3 = pk2(A[3], B[3]), q4 = pk2(A[4], B[4]), q5 = pk2(A[5], B[5]);
        u64 q6 = pk2(A[6], B[6]), q7 = pk2(A[7], B[7]), q8 = pk2(A[8], B[8]);

        // ---- G = X^T X (row passes, slot-A shared; doubles as sum-sq) ----
        u64 g00 = mul2(q0, q0);
        u64 g01 = mul2(q0, q1);
        u64 g02 = mul2(q0, q2);
        u64 g11 = mul2(q1, q1);
        u64 g12 = mul2(q1, q2);
        u64 g22 = mul2(q2, q2);

        g00 = fma2(q3, q3, g00);
        g01 = fma2(q3, q4, g01);
        g02 = fma2(q3, q5, g02);
        g11 = fma2(q4, q4, g11);
        g12 = fma2(q4, q5, g12);
        g22 = fma2(q5, q5, g22);

        g00 = fma2(q6, q6, g00);
        g01 = fma2(q6, q7, g01);
        g02 = fma2(q6, q8, g02);
        g11 = fma2(q7, q7, g11);
        g12 = fma2(q7, q8, g12);
        g22 = fma2(q8, q8, g22);

        // ss = trace(G) = ||X||_F^2 ; inv = 1/||X||, inv2 = 1/||X||^2
        u64 ssum = add2(add2(g00, g11), g22);
        float sa, sbf; upk2(ssum, sa, sbf);
        const u64 inv  = pk2(rsqrtf(sa), rsqrtf(sbf));
        const u64 inv2 = mul2(inv, inv);

        // S0 = inv2*G - 1.5I  (slot-A = inv2 shared)
        u64 s00 = fma2(inv2, g00, C_M15);
        u64 s01 = mul2(inv2, g01);
        u64 s02 = mul2(inv2, g02);
        u64 s11 = fma2(inv2, g11, C_M15);
        u64 s12 = mul2(inv2, g12);
        u64 s22 = fma2(inv2, g22, C_M15);

        // ---- layer 0 (M scaled by inv: Q1 = X * (inv*M0)) ----
        {
            u64 t00 = mul2(s00, s00);
            u64 t01 = mul2(s00, s01);
            u64 t02 = mul2(s00, s02);
            u64 t11 = mul2(s01, s01);
            u64 t12 = mul2(s01, s02);
            u64 t22 = mul2(s02, s02);

            t00 = fma2(s01, s01, t00);
            t01 = fma2(s01, s11, t01);
            t02 = fma2(s01, s12, t02);
            t11 = fma2(s11, s11, t11);
            t12 = fma2(s11, s12, t12);
            t22 = fma2(s12, s12, t22);

            t00 = fma2(s02, s02, t00);
            t01 = fma2(s02, s12, t01);
            t02 = fma2(s02, s22, t02);
            t11 = fma2(s12, s12, t11);
            t12 = fma2(s12, s22, t12);
            t22 = fma2(s22, s22, t22);

            const u64 ch = mul2(C_HALF, inv);   // 0.5/||X||
            const u64 c8 = mul2(C_7o8, inv);    // 0.875/||X||
            u64 m00 = fma2(ch, t00, c8);
            u64 m01 = mul2(ch, t01);
            u64 m02 = mul2(ch, t02);
            u64 m11 = fma2(ch, t11, c8);
            u64 m12 = mul2(ch, t12);
            u64 m22 = fma2(ch, t22, c8);

            u64 r0 = mul2(q0, m00);
            u64 r1 = mul2(q0, m01);
            u64 r2 = mul2(q0, m02);
            u64 r3 = mul2(q3, m00);
            u64 r4 = mul2(q3, m01);
            u64 r5 = mul2(q3, m02);
            u64 r6 = mul2(q6, m00);
            u64 r7 = mul2(q6, m01);
            u64 r8 = mul2(q6, m02);

            r0 = fma2(q1, m01, r0);
            r1 = fma2(q1, m11, r1);
            r2 = fma2(q1, m12, r2);
            r3 = fma2(q4, m01, r3);
            r4 = fma2(q4, m11, r4);
            r5 = fma2(q4, m12, r5);
            r6 = fma2(q7, m01, r6);
            r7 = fma2(q7, m11, r7);
            r8 = fma2(q7, m12, r8);

            q0 = fma2(q2, m02, r0);
            q1 = fma2(q2, m12, r1);
            q2 = fma2(q2, m22, r2);
            q3 = fma2(q5, m02, r3);
            q4 = fma2(q5, m12, r4);
            q5 = fma2(q5, m22, r5);
            q6 = fma2(q8, m02, r6);
            q7 = fma2(q8, m12, r7);
            q8 = fma2(q8, m22, r8);
        }

        // ---- layers 1..3 (R10 body) ----
        #pragma unroll
        for (int layer = 0; layer < 3; ++layer) {
            u64 s00 = fma2(q0, q0, C_M15);
            u64 s01 = mul2(q0, q1);
            u64 s02 = mul2(q0, q2);
            u64 s11 = fma2(q1, q1, C_M15);
            u64 s12 = mul2(q1, q2);
            u64 s22 = fma2(q2, q2, C_M15);

            s00 = fma2(q3, q3, s00);
            s01 = fma2(q3, q4, s01);
            s02 = fma2(q3, q5, s02);
            s11 = fma2(q4, q4, s11);
            s12 = fma2(q4, q5, s12);
            s22 = fma2(q5, q5, s22);

            s00 = fma2(q6, q6, s00);
            s01 = fma2(q6, q7, s01);
            s02 = fma2(q6, q8, s02);
            s11 = fma2(q7, q7, s11);
            s12 = fma2(q7, q8, s12);
            s22 = fma2(q8, q8, s22);

            u64 t00 = mul2(s00, s00);
            u64 t01 = mul2(s00, s01);
            u64 t02 = mul2(s00, s02);
            u64 t11 = mul2(s01, s01);
            u64 t12 = mul2(s01, s02);
            u64 t22 = mul2(s02, s02);

            t00 = fma2(s01, s01, t00);
            t01 = fma2(s01, s11, t01);
            t02 = fma2(s01, s12, t02);
            t11 = fma2(s11, s11, t11);
            t12 = fma2(s11, s12, t12);
            t22 = fma2(s12, s12, t22);

            t00 = fma2(s02, s02, t00);
            t01 = fma2(s02, s12, t01);
            t02 = fma2(s02, s22, t02);
            t11 = fma2(s12, s12, t11);
            t12 = fma2(s12, s22, t12);
            t22 = fma2(s22, s22, t22);

            u64 m00 = fma2(C_HALF, t00, C_7o8);
            u64 m01 = mul2(C_HALF, t01);
            u64 m02 = mul2(C_HALF, t02);
            u64 m11 = fma2(C_HALF, t11, C_7o8);
            u64 m12 = mul2(C_HALF, t12);
            u64 m22 = fma2(C_HALF, t22, C_7o8);

            u64 r0 = mul2(q0, m00);
            u64 r1 = mul2(q0, m01);
            u64 r2 = mul2(q0, m02);
            u64 r3 = mul2(q3, m00);
            u64 r4 = mul2(q3, m01);
            u64 r5 = mul2(q3, m02);
            u64 r6 = mul2(q6, m00);
            u64 r7 = mul2(q6, m01);
            u64 r8 = mul2(q6, m02);

            r0 = fma2(q1, m01, r0);
            r1 = fma2(q1, m11, r1);
            r2 = fma2(q1, m12, r2);
            r3 = fma2(q4, m01, r3);
            r4 = fma2(q4, m11, r4);
            r5 = fma2(q4, m12, r5);
            r6 = fma2(q7, m01, r6);
            r7 = fma2(q7, m11, r7);
            r8 = fma2(q7, m12, r8);

            q0 = fma2(q2, m02, r0);
            q1 = fma2(q2, m12, r1);
            q2 = fma2(q2, m22, r2);
            q3 = fma2(q5, m02, r3);
            q4 = fma2(q5, m12, r4);
            q5 = fma2(q5, m22, r5);
            q6 = fma2(q8, m02, r6);
            q7 = fma2(q8, m12, r7);
            q8 = fma2(q8, m22, r8);
        }

        // ---- writeback: scalar halves (pair halves are free) ----
        {
            float* WA = &smem[wid][buf][lane * 9];
            float* WB = WA + 32 * 9;
            float x, y;
            upk2(q0, x, y); WA[0] = x; WB[0] = y;
            upk2(q1, x, y); WA[1] = x; WB[1] = y;
            upk2(q2, x, y); WA[2] = x; WB[2] = y;
            upk2(q3, x, y); WA[3] = x; WB[3] = y;
            upk2(q4, x, y); WA[4] = x; WB[4] = y;
            upk2(q5, x, y); WA[5] = x; WB[5] = y;
            upk2(q6, x, y); WA[6] = x; WB[6] = y;
            upk2(q7, x, y); WA[7] = x; WB[7] = y;
            upk2(q8, x, y); WA[8] = x; WB[8] = y;
        }
        __syncwarp();

        // ---- copy out: one TMA bulk store per warp-tile ----
        if (lane == 0) {
            fence_async_shared();
            bulk_store(gdst, sb[buf], WFLB);
            bulk_commit();
        }
        gdst += stepB;
    }

    if (lane == 0) bulk_wait_all0();
}

extern "C" void kernel_launch(void* const* d_in, const int* in_sizes, int n_in,
                              void* d_out, int out_size)
{
    const float* x = (const float*)d_in[0];
    float* out = (float*)d_out;
    const int n_mat = in_sizes[0] / 9;          // 4,000,000
    const int n_wt  = n_mat / WMT;              // 62,500 full warp-tiles
    int grid = 152 * 9;                         // 9 CTAs/SM, 36 warps/SM
    const int max_grid = (n_wt + WARPS - 1) / WARPS;
    if (grid > max_grid) grid = max_grid;
    if (grid < 1) grid = 1;
    strict_projection_kernel<<<grid, THREADS>>>(x, out, n_mat, n_wt);
}

// round 13
// speedup vs baseline: 1.0883x; 1.0484x over previous
#include <cuda_runtime.h>
#include <cstdint>

// StrictProjectionBlock: 4M independent 3x3 fp32 matrices.
//   Q = X/||X||_F ; 4x:  S = Q^T Q - 1.5I;  Q <- Q * (0.5*S^2 + 0.875I)
//
// R13 = R10 (best measured: depth-2 cp.async loads, TMA bulk stores, packed
// fp32x2, strided lane->matrix, pass-ordered FMAs, 9 CTAs/SM / 36 warps)
// + #pragma unroll 2 on the persistent loop so ptxas can software-pipeline
// the next tile's LDS/address work into the current tile's FMA stretch.

using u64 = unsigned long long;

__device__ __forceinline__ u64 pk2(float lo, float hi) {
    u64 r; asm("mov.b64 %0, {%1,%2};" : "=l"(r) : "f"(lo), "f"(hi)); return r;
}
__device__ __forceinline__ void upk2(u64 v, float& lo, float& hi) {
    asm("mov.b64 {%0,%1}, %2;" : "=f"(lo), "=f"(hi) : "l"(v));
}
__device__ __forceinline__ u64 fma2(u64 a, u64 b, u64 c) {
    u64 d; asm("fma.rn.f32x2 %0, %1, %2, %3;" : "=l"(d) : "l"(a), "l"(b), "l"(c)); return d;
}
__device__ __forceinline__ u64 mul2(u64 a, u64 b) {
    u64 d; asm("mul.rn.f32x2 %0, %1, %2;" : "=l"(d) : "l"(a), "l"(b)); return d;
}
__device__ __forceinline__ uint32_t smem_u32(const void* p) {
    uint32_t a;
    asm("{ .reg .u64 t; cvta.to.shared.u64 t, %1; cvt.u32.u64 %0, t; }" : "=r"(a) : "l"(p));
    return a;
}
__device__ __forceinline__ void cpa16(uint32_t s, const void* g) {
    asm volatile("cp.async.cg.shared.global [%0], [%1], 16;" :: "r"(s), "l"(g));
}
__device__ __forceinline__ void cpa_commit() { asm volatile("cp.async.commit_group;"); }
__device__ __forceinline__ void cpa_wait1()  { asm volatile("cp.async.wait_group 1;"); }
__device__ __forceinline__ void cpa_wait0()  { asm volatile("cp.async.wait_group 0;"); }

__device__ __forceinline__ void bulk_store(u64 gdst, uint32_t ssrc, uint32_t bytes) {
    asm volatile("cp.async.bulk.global.shared::cta.bulk_group [%0], [%1], %2;"
                 :: "l"(gdst), "r"(ssrc), "r"(bytes) : "memory");
}
__device__ __forceinline__ void bulk_commit() {
    asm volatile("cp.async.bulk.commit_group;" ::: "memory");
}
__device__ __forceinline__ void bulk_wait_read0() {
    asm volatile("cp.async.bulk.wait_group.read 0;" ::: "memory");
}
__device__ __forceinline__ void bulk_wait_all0() {
    asm volatile("cp.async.bulk.wait_group 0;" ::: "memory");
}
__device__ __forceinline__ void fence_async_shared() {
    asm volatile("fence.proxy.async.shared::cta;" ::: "memory");
}

constexpr int THREADS = 128;
constexpr int WARPS   = THREADS / 32;     // 4
constexpr int WMT     = 64;               // matrices per warp-tile (2/thread)
constexpr int WFL     = WMT * 9;          // 576 floats
constexpr int WFLB    = WFL * 4;          // 2304 bytes per tile

constexpr u64 C_HALF = 0x3F0000003F000000ULL;  // ( 0.5  , 0.5  )
constexpr u64 C_M15  = 0xBFC00000BFC00000ULL;  // (-1.5  ,-1.5  )
constexpr u64 C_7o8  = 0x3F6000003F600000ULL;  // ( 0.875, 0.875)

// scalar fallback for remainder matrices (n_mat % 64 != 0; unused for 4M)
__device__ void project1(float* q) {
    float ss = 0.f;
    #pragma unroll
    for (int i = 0; i < 9; i++) ss += q[i] * q[i];
    float inv = rsqrtf(ss);
    #pragma unroll
    for (int i = 0; i < 9; i++) q[i] *= inv;
    #pragma unroll
    for (int l = 0; l < 4; l++) {
        float n00 = q[0]*q[0]+q[3]*q[3]+q[6]*q[6];
        float n01 = q[0]*q[1]+q[3]*q[4]+q[6]*q[7];
        float n02 = q[0]*q[2]+q[3]*q[5]+q[6]*q[8];
        float n11 = q[1]*q[1]+q[4]*q[4]+q[7]*q[7];
        float n12 = q[1]*q[2]+q[4]*q[5]+q[7]*q[8];
        float n22 = q[2]*q[2]+q[5]*q[5]+q[8]*q[8];
        float s00 = n00-1.5f, s11 = n11-1.5f, s22 = n22-1.5f;
        float m00 = 0.5f*(s00*s00+n01*n01+n02*n02)+0.875f;
        float m01 = 0.5f*(s00*n01+n01*s11+n02*n12);
        float m02 = 0.5f*(s00*n02+n01*n12+n02*s22);
        float m11 = 0.5f*(n01*n01+s11*s11+n12*n12)+0.875f;
        float m12 = 0.5f*(n01*n02+s11*n12+n12*s22);
        float m22 = 0.5f*(n02*n02+n12*n12+s22*s22)+0.875f;
        float r0 = q[0]*m00+q[1]*m01+q[2]*m02;
        float r1 = q[0]*m01+q[1]*m11+q[2]*m12;
        float r2 = q[0]*m02+q[1]*m12+q[2]*m22;
        float r3 = q[3]*m00+q[4]*m01+q[5]*m02;
        float r4 = q[3]*m01+q[4]*m11+q[5]*m12;
        float r5 = q[3]*m02+q[4]*m12+q[5]*m22;
        float r6 = q[6]*m00+q[7]*m01+q[8]*m02;
        float r7 = q[6]*m01+q[7]*m11+q[8]*m12;
        float r8 = q[6]*m02+q[7]*m12+q[8]*m22;
        q[0]=r0; q[1]=r1; q[2]=r2; q[3]=r3; q[4]=r4;
        q[5]=r5; q[6]=r6; q[7]=r7; q[8]=r8;
    }
}

__global__ void __launch_bounds__(THREADS, 9)
strict_projection_kernel(const float* __restrict__ in,
                         float* __restrict__ out,
                         int n_mat, int n_wt)
{
    __shared__ float smem[WARPS][2][WFL];    // 18,432 B -> 9 CTAs/SM

    const int lane = threadIdx.x & 31;
    const int wid  = threadIdx.x >> 5;

    // ---- remainder matrices (n_mat % 64), block 0 / warp 0 ----
    if (blockIdx.x == 0 && wid == 0) {
        const int rem_base = n_wt * WMT;
        for (int m = rem_base + lane; m < n_mat; m += 32) {
            float q[9];
            #pragma unroll
            for (int i = 0; i < 9; i++) q[i] = in[(size_t)m * 9 + i];
            project1(q);
            #pragma unroll
            for (int i = 0; i < 9; i++) out[(size_t)m * 9 + i] = q[i];
        }
    }

    const int wgid    = blockIdx.x * WARPS + wid;
    const int wstride = gridDim.x * WARPS;
    if (wgid >= n_wt) return;

    const uint32_t sb[2] = { smem_u32(&smem[wid][0][0]), smem_u32(&smem[wid][1][0]) };

    const size_t stepB = (size_t)wstride * WFLB;
    const float4* gpre = reinterpret_cast<const float4*>(in) + (size_t)wgid * (WFL / 4);
    u64 gdst = (u64)(uintptr_t)out + (u64)wgid * WFLB;

    auto prefetch = [&](const float4* g, uint32_t s) {
        #pragma unroll
        for (int k = 0; k < 4; k++)
            cpa16(s + (uint32_t)(lane + 32 * k) * 16u, g + lane + 32 * k);
        if (lane < 16)
            cpa16(s + (uint32_t)(128 + lane) * 16u, g + 128 + lane);
    };

    prefetch(gpre, sb[0]);
    cpa_commit();
    gpre += stepB / 16;

    int buf = 0;
    #pragma unroll 2
    for (int t = wgid; t < n_wt; t += wstride, buf ^= 1) {
        const bool have_next = (t + wstride) < n_wt;
        if (have_next) {
            if (lane == 0) bulk_wait_read0();   // TMA done reading buf^1
            __syncwarp();
            prefetch(gpre, sb[buf ^ 1]);
            cpa_commit();
            cpa_wait1();
            gpre += stepB / 16;
        } else {
            cpa_wait0();
        }
        __syncwarp();

        // ---- strided lane->matrix: A = tile[lane], B = tile[lane+32] ----
        const float* A = &smem[wid][buf][lane * 9];
        const float* B = A + 32 * 9;

        u64 q0 = pk2(A[0], B[0]), q1 = pk2(A[1], B[1]), q2 = pk2(A[2], B[2]);
        u64 q3 = pk2(A[3], B[3]), q4 = pk2(A[4], B[4]), q5 = pk2(A[5], B[5]);
        u64 q6 = pk2(A[6], B[6]), q7 = pk2(A[7], B[7]), q8 = pk2(A[8], B[8]);

        // ---- Frobenius normalize ----
        u64 ss = mul2(q0, q0);
        ss = fma2(q1, q1, ss); ss = fma2(q2, q2, ss);
        ss = fma2(q3, q3, ss); ss = fma2(q4, q4, ss);
        ss = fma2(q5, q5, ss); ss = fma2(q6, q6, ss);
        ss = fma2(q7, q7, ss); ss = fma2(q8, q8, ss);
        float sa, sbf; upk2(ss, sa, sbf);
        const u64 inv = pk2(rsqrtf(sa), rsqrtf(sbf));
        q0 = mul2(q0, inv); q1 = mul2(q1, inv); q2 = mul2(q2, inv);
        q3 = mul2(q3, inv); q4 = mul2(q4, inv); q5 = mul2(q5, inv);
        q6 = mul2(q6, inv); q7 = mul2(q7, inv); q8 = mul2(q8, inv);

        #pragma unroll
        for (int layer = 0; layer < 4; ++layer) {
            // S = Q^T Q - 1.5I : row passes, slot-A shared within pass
            u64 s00 = fma2(q0, q0, C_M15);
            u64 s01 = mul2(q0, q1);
            u64 s02 = mul2(q0, q2);
            u64 s11 = fma2(q1, q1, C_M15);
            u64 s12 = mul2(q1, q2);
            u64 s22 = fma2(q2, q2, C_M15);

            s00 = fma2(q3, q3, s00);
            s01 = fma2(q3, q4, s01);
            s02 = fma2(q3, q5, s02);
            s11 = fma2(q4, q4, s11);
            s12 = fma2(q4, q5, s12);
            s22 = fma2(q5, q5, s22);

            s00 = fma2(q6, q6, s00);
            s01 = fma2(q6, q7, s01);
            s02 = fma2(q6, q8, s02);
            s11 = fma2(q7, q7, s11);
            s12 = fma2(q7, q8, s12);
            s22 = fma2(q8, q8, s22);

            // T = S^2 : row passes over S
            u64 t00 = mul2(s00, s00);
            u64 t01 = mul2(s00, s01);
            u64 t02 = mul2(s00, s02);
            u64 t11 = mul2(s01, s01);
            u64 t12 = mul2(s01, s02);
            u64 t22 = mul2(s02, s02);

            t00 = fma2(s01, s01, t00);
            t01 = fma2(s01, s11, t01);
            t02 = fma2(s01, s12, t02);
            t11 = fma2(s11, s11, t11);
            t12 = fma2(s11, s12, t12);
            t22 = fma2(s12, s12, t22);

            t00 = fma2(s02, s02, t00);
            t01 = fma2(s02, s12, t01);
            t02 = fma2(s02, s22, t02);
            t11 = fma2(s12, s12, t11);
            t12 = fma2(s12, s22, t12);
            t22 = fma2(s22, s22, t22);

            // M = 0.5*T + 0.875I
            u64 m00 = fma2(C_HALF, t00, C_7o8);
            u64 m01 = mul2(C_HALF, t01);
            u64 m02 = mul2(C_HALF, t02);
            u64 m11 = fma2(C_HALF, t11, C_7o8);
            u64 m12 = mul2(C_HALF, t12);
            u64 m22 = fma2(C_HALF, t22, C_7o8);

            // R = Q * M : k-passes, slot-A shared per pass
            u64 r0 = mul2(q0, m00);
            u64 r1 = mul2(q0, m01);
            u64 r2 = mul2(q0, m02);
            u64 r3 = mul2(q3, m00);
            u64 r4 = mul2(q3, m01);
            u64 r5 = mul2(q3, m02);
            u64 r6 = mul2(q6, m00);
            u64 r7 = mul2(q6, m01);
            u64 r8 = mul2(q6, m02);

            r0 = fma2(q1, m01, r0);
            r1 = fma2(q1, m11, r1);
            r2 = fma2(q1, m12, r2);
            r3 = fma2(q4, m01, r3);
            r4 = fma2(q4, m11, r4);
            r5 = fma2(q4, m12, r5);
            r6 = fma2(q7, m01, r6);
            r7 = fma2(q7, m11, r7);
            r8 = fma2(q7, m12, r8);

            q0 = fma2(q2, m02, r0);
            q1 = fma2(q2, m12, r1);
            q2 = fma2(q2, m22, r2);
            q3 = fma2(q5, m02, r3);
            q4 = fma2(q5, m12, r4);
            q5 = fma2(q5, m22, r5);
            q6 = fma2(q8, m02, r6);
            q7 = fma2(q8, m12, r7);
            q8 = fma2(q8, m22, r8);
        }

        // ---- writeback: scalar halves (pair halves are free) ----
        {
            float* WA = &smem[wid][buf][lane * 9];
            float* WB = WA + 32 * 9;
            float x, y;
            upk2(q0, x, y); WA[0] = x; WB[0] = y;
            upk2(q1, x, y); WA[1] = x; WB[1] = y;
            upk2(q2, x, y); WA[2] = x; WB[2] = y;
            upk2(q3, x, y); WA[3] = x; WB[3] = y;
            upk2(q4, x, y); WA[4] = x; WB[4] = y;
            upk2(q5, x, y); WA[5] = x; WB[5] = y;
            upk2(q6, x, y); WA[6] = x; WB[6] = y;
            upk2(q7, x, y); WA[7] = x; WB[7] = y;
            upk2(q8, x, y); WA[8] = x; WB[8] = y;
        }
        __syncwarp();

        // ---- copy out: one TMA bulk store per warp-tile ----
        if (lane == 0) {
            fence_async_shared();
            bulk_store(gdst, sb[buf], WFLB);
            bulk_commit();
        }
        gdst += stepB;
    }

    if (lane == 0) bulk_wait_all0();
}

extern "C" void kernel_launch(void* const* d_in, const int* in_sizes, int n_in,
                              void* d_out, int out_size)
{
    const float* x = (const float*)d_in[0];
    float* out = (float*)d_out;
    const int n_mat = in_sizes[0] / 9;          // 4,000,000
    const int n_wt  = n_mat / WMT;              // 62,500 full warp-tiles
    int grid = 152 * 9;                         // 9 CTAs/SM, 36 warps/SM
    const int max_grid = (n_wt + WARPS - 1) / WARPS;
    if (grid > max_grid) grid = max_grid;
    if (grid < 1) grid = 1;
    strict_projection_kernel<<<grid, THREADS>>>(x, out, n_mat, n_wt);
}